// round 13
// baseline (speedup 1.0000x reference)
#include <cuda_runtime.h>
#include <cuda_fp16.h>
#include <cstdint>
#include <math.h>

// Problem constants
#define B       2
#define S       2048
#define D       1024
#define HEADS   16
#define DH      64
#define INNER   1024
#define D3      3072
#define ROWS    4096
#define LN_EPS  1e-5f
// 0.125 * log2(e): applied to S inside softmax (fma), Q stays raw fp16
#define QSCALE_LOG2E 0.18033688011112042f

// Scratch: xn(half) | qkv(half) | ctx(half) | w_qkv^T(half) | w_out^T(half)
__device__ float g_scratch[(size_t)ROWS * D + (size_t)ROWS * D3 + (size_t)ROWS * D
                           + (size_t)D * D3 + (size_t)D * D];

// ---------------------------------------------------------------------------
// Helpers
// ---------------------------------------------------------------------------
__device__ __forceinline__ uint32_t smem_u32(const void* p) {
    uint32_t a;
    asm("{ .reg .u64 t; cvta.to.shared.u64 t, %1; cvt.u32.u64 %0, t; }" : "=r"(a) : "l"(p));
    return a;
}
__device__ __forceinline__ float ex2f(float x) {
    float r;
    asm("ex2.approx.ftz.f32 %0, %1;" : "=f"(r) : "f"(x));
    return r;
}
__device__ __forceinline__ uint32_t packh2(float lo, float hi) {
    __half2 h = __floats2half2_rn(lo, hi);
    return *(uint32_t*)&h;
}

#define CP_ASYNC16(dst, src) \
    asm volatile("cp.async.cg.shared.global [%0], [%1], 16;" :: "r"(dst), "l"(src))
#define CP_COMMIT()  asm volatile("cp.async.commit_group;" ::: "memory")
#define CP_WAIT1()   asm volatile("cp.async.wait_group 1;" ::: "memory")
#define CP_WAIT0()   asm volatile("cp.async.wait_group 0;" ::: "memory")

__device__ __forceinline__ void mma_f16(
    float& d0, float& d1, float& d2, float& d3,
    uint32_t a0, uint32_t a1, uint32_t a2, uint32_t a3,
    uint32_t b0, uint32_t b1)
{
    asm volatile(
        "mma.sync.aligned.m16n8k16.row.col.f32.f16.f16.f32 "
        "{%0,%1,%2,%3}, {%4,%5,%6,%7}, {%8,%9}, {%0,%1,%2,%3};"
        : "+f"(d0), "+f"(d1), "+f"(d2), "+f"(d3)
        : "r"(a0), "r"(a1), "r"(a2), "r"(a3), "r"(b0), "r"(b1));
}
#define LDSM_X4(r0, r1, r2, r3, addr) \
    asm volatile("ldmatrix.sync.aligned.m8n8.x4.shared.b16 {%0,%1,%2,%3}, [%4];" \
        : "=r"(r0), "=r"(r1), "=r"(r2), "=r"(r3) : "r"(addr))
#define LDSM_X4_T(r0, r1, r2, r3, addr) \
    asm volatile("ldmatrix.sync.aligned.m8n8.x4.trans.shared.b16 {%0,%1,%2,%3}, [%4];" \
        : "=r"(r0), "=r"(r1), "=r"(r2), "=r"(r3) : "r"(addr))

// ---------------------------------------------------------------------------
// LayerNorm (output written as fp16, rn)
// ---------------------------------------------------------------------------
__global__ __launch_bounds__(256) void ln_kernel(
    const float* __restrict__ x, const float* __restrict__ gamma,
    const float* __restrict__ beta, uint32_t* __restrict__ y)
{
    const int row = blockIdx.x;
    const int t = threadIdx.x;
    const float4* xp = (const float4*)(x + (size_t)row * D);
    float4 v = xp[t];
    float s  = v.x + v.y + v.z + v.w;
    float ss = v.x * v.x + v.y * v.y + v.z * v.z + v.w * v.w;
    #pragma unroll
    for (int off = 16; off > 0; off >>= 1) {
        s  += __shfl_down_sync(0xffffffffu, s,  off);
        ss += __shfl_down_sync(0xffffffffu, ss, off);
    }
    __shared__ float sh_s[8], sh_ss[8];
    const int w = t >> 5, lane = t & 31;
    if (lane == 0) { sh_s[w] = s; sh_ss[w] = ss; }
    __syncthreads();
    __shared__ float mu_sh, rstd_sh;
    if (t == 0) {
        float S0 = 0.f, SS0 = 0.f;
        #pragma unroll
        for (int i = 0; i < 8; i++) { S0 += sh_s[i]; SS0 += sh_ss[i]; }
        const float mu  = S0 * (1.0f / D);
        const float var = SS0 * (1.0f / D) - mu * mu;
        mu_sh = mu;
        rstd_sh = rsqrtf(var + LN_EPS);
    }
    __syncthreads();
    const float mu = mu_sh, rstd = rstd_sh;
    float4 g  = ((const float4*)gamma)[t];
    float4 bb = ((const float4*)beta)[t];
    const float ox = (v.x - mu) * rstd * g.x + bb.x;
    const float oy = (v.y - mu) * rstd * g.y + bb.y;
    const float oz = (v.z - mu) * rstd * g.z + bb.z;
    const float ow = (v.w - mu) * rstd * g.w + bb.w;
    ((uint2*)(y + (size_t)row * (D / 2)))[t] = make_uint2(packh2(ox, oy), packh2(oz, ow));
}

// ---------------------------------------------------------------------------
// Pack + transpose weights: W[K=1024][N] f32 -> WT[N][K=1024] fp16.
// grid (N/32, 32), block (32, 8)
// ---------------------------------------------------------------------------
__global__ __launch_bounds__(256) void pack_wT_kernel(
    const float* __restrict__ W, __half* __restrict__ WT, int N)
{
    __shared__ float tile[32][33];
    const int n0 = blockIdx.x * 32, k0 = blockIdx.y * 32;
    const int tx = threadIdx.x, ty = threadIdx.y;
    #pragma unroll
    for (int j = 0; j < 32; j += 8)
        tile[ty + j][tx] = W[(size_t)(k0 + ty + j) * N + n0 + tx];
    __syncthreads();
    #pragma unroll
    for (int j = 0; j < 32; j += 8)
        WT[(size_t)(n0 + ty + j) * D + k0 + tx] = __float2half_rn(tile[tx][ty + j]);
}

// ---------------------------------------------------------------------------
// FP16 mma.sync GEMM with ldmatrix fragments, BK=64:
// C = A[M,1024] @ WT[N,1024]^T (+bias), f32 accumulate.
// 128x128 tile, 256 threads, 8 warps (warp-tile 32x64), 2-stage cp.async.
// 24 ldmatrix + 64 HMMA per barrier interval (2x R12's work/barrier).
// smem pitch 72 halves (ldmatrix conflict-free, attention-proven).
// Output: fp32 (Cf) or packed fp16 (Ch).
// ---------------------------------------------------------------------------
#define GP 72
#define G_ST (128 * GP)                    // halves per operand per stage
#define GEMM_SMEM (2 * 2 * G_ST * 2)       // 73728 B

__global__ __launch_bounds__(256, 2) void gemm_h_kernel(
    const __half* __restrict__ A, const __half* __restrict__ WT,
    const float* __restrict__ bias, float* __restrict__ Cf,
    uint32_t* __restrict__ Ch, int N)
{
    extern __shared__ char smc[];
    const uint32_t aB[2] = { smem_u32(smc),            smem_u32(smc) + G_ST * 2 };
    const uint32_t bB[2] = { aB[1] + G_ST * 2,         aB[1] + 2 * G_ST * 2 };

    const int tid = threadIdx.x;
    const int wid = tid >> 5, lane = tid & 31;
    const int gID = lane >> 2, tg = lane & 3;
    const int rowl = lane & 7, grp = lane >> 3;
    const int bm = blockIdx.y * 128, bn = blockIdx.x * 128;
    const int wm = (wid & 3) * 32, wn = (wid >> 2) * 64;

    // ldmatrix lane offsets (halves)
    // A: r0=(m0-7,klo) r1=(m8-15,klo) r2=(m0-7,khi) r3=(m8-15,khi)
    const uint32_t aOff = (uint32_t)(((grp & 1) * 8 + rowl) * GP + (grp >> 1) * 8);
    // B: r0=(nlo,klo) r1=(nlo,khi) r2=(nhi,klo) r3=(nhi,khi)
    const uint32_t bOff = (uint32_t)(((grp >> 1) * 8 + rowl) * GP + (grp & 1) * 8);

    float acc[2][8][4];
    #pragma unroll
    for (int im = 0; im < 2; im++)
        #pragma unroll
        for (int n = 0; n < 8; n++)
            #pragma unroll
            for (int j = 0; j < 4; j++) acc[im][n][j] = 0.f;

    // prologue: chunks 0,1 (BK=64: 128 rows x 8 chunks of 16B per operand)
    #pragma unroll
    for (int pi = 0; pi < 2; pi++) {
        const int k0 = pi * 64;
        #pragma unroll
        for (int j = 0; j < 4; j++) {
            const int idx = tid + j * 256;
            const int r = idx >> 3, c = idx & 7;
            CP_ASYNC16(aB[pi] + (uint32_t)(r * GP + c * 8) * 2u,
                       A + (size_t)(bm + r) * D + k0 + c * 8);
            CP_ASYNC16(bB[pi] + (uint32_t)(r * GP + c * 8) * 2u,
                       WT + (size_t)(bn + r) * D + k0 + c * 8);
        }
        CP_COMMIT();
    }

    for (int i = 0; i < 16; i++) {
        const int s = i & 1;
        if (i < 15) { CP_WAIT1(); } else { CP_WAIT0(); }
        __syncthreads();
        const uint32_t aS = aB[s], bS = bB[s];
        #pragma unroll
        for (int ks = 0; ks < 4; ks++) {
            uint32_t af[2][4];
            #pragma unroll
            for (int im = 0; im < 2; im++)
                LDSM_X4(af[im][0], af[im][1], af[im][2], af[im][3],
                        aS + (aOff + (uint32_t)((wm + im * 16) * GP + ks * 16)) * 2u);
            #pragma unroll
            for (int np = 0; np < 4; np++) {
                uint32_t b0, b1, b2, b3;
                LDSM_X4(b0, b1, b2, b3,
                        bS + (bOff + (uint32_t)((wn + np * 16) * GP + ks * 16)) * 2u);
                #pragma unroll
                for (int im = 0; im < 2; im++) {
                    mma_f16(acc[im][2*np][0], acc[im][2*np][1],
                            acc[im][2*np][2], acc[im][2*np][3],
                            af[im][0], af[im][1], af[im][2], af[im][3], b0, b1);
                    mma_f16(acc[im][2*np+1][0], acc[im][2*np+1][1],
                            acc[im][2*np+1][2], acc[im][2*np+1][3],
                            af[im][0], af[im][1], af[im][2], af[im][3], b2, b3);
                }
            }
        }
        __syncthreads();
        if (i + 2 < 16) {
            const int k0 = (i + 2) * 64;
            #pragma unroll
            for (int j = 0; j < 4; j++) {
                const int idx = tid + j * 256;
                const int r = idx >> 3, c = idx & 7;
                CP_ASYNC16(aB[s] + (uint32_t)(r * GP + c * 8) * 2u,
                           A + (size_t)(bm + r) * D + k0 + c * 8);
                CP_ASYNC16(bB[s] + (uint32_t)(r * GP + c * 8) * 2u,
                           WT + (size_t)(bn + r) * D + k0 + c * 8);
            }
            CP_COMMIT();
        }
    }

    // epilogue (acc: rows gID,gID+8; cols 2tg,2tg+1 within each n*8 group)
    #pragma unroll
    for (int im = 0; im < 2; im++) {
        const int r0 = bm + wm + im * 16 + gID;
        #pragma unroll
        for (int n = 0; n < 8; n++) {
            const int col = bn + wn + n * 8 + 2 * tg;
            float v0 = acc[im][n][0], v1 = acc[im][n][1];
            float v2 = acc[im][n][2], v3 = acc[im][n][3];
            if (bias) {
                const float b0 = bias[col], b1 = bias[col + 1];
                v0 += b0; v1 += b1; v2 += b0; v3 += b1;
            }
            if (Ch) {
                Ch[((size_t)r0 * N + col) >> 1]       = packh2(v0, v1);
                Ch[((size_t)(r0 + 8) * N + col) >> 1] = packh2(v2, v3);
            } else {
                *(float2*)&Cf[(size_t)r0 * N + col]       = make_float2(v0, v1);
                *(float2*)&Cf[(size_t)(r0 + 8) * N + col] = make_float2(v2, v3);
            }
        }
    }
}

// ---------------------------------------------------------------------------
// FP16 mma.sync flash attention (R11-good version, unchanged).
// ---------------------------------------------------------------------------
#define KPH 72
#define KV_TILE_B (64 * KPH * 2)            // 9216 B per K or V stage
#define ATTN_SMEM (2 * 2 * KV_TILE_B)       // 36864 B

__global__ __launch_bounds__(256, 2) void attn_kernel(
    const __half* __restrict__ qkv, uint32_t* __restrict__ ctxh)
{
    extern __shared__ char smc[];
    const uint32_t kB[2] = { smem_u32(smc),                 smem_u32(smc) + KV_TILE_B };
    const uint32_t vB[2] = { kB[0] + 2 * KV_TILE_B,         kB[1] + 2 * KV_TILE_B };

    const int tid = threadIdx.x;
    const int wid = tid >> 5, lane = tid & 31;
    const int gID = lane >> 2, tg = lane & 3;
    const int rowl = lane & 7, grp = lane >> 3;
    const int h = blockIdx.y, bb = blockIdx.z;
    const int qbase = blockIdx.x * 128 + wid * 16;

    const __half* qp = qkv + (size_t)(bb * S + qbase) * D3 + h * DH;
    const __half* kbase = qkv + (size_t)bb * S * D3 + INNER + h * DH;
    const __half* vbase = kbase + INNER;

    // Q fragments: raw fp16, u32 pair slots
    uint32_t qa[4][4];
    #pragma unroll
    for (int ks = 0; ks < 4; ks++) {
        qa[ks][0] = *(const uint32_t*)(qp + (size_t)gID * D3 + 16 * ks + 2 * tg);
        qa[ks][1] = *(const uint32_t*)(qp + (size_t)(gID + 8) * D3 + 16 * ks + 2 * tg);
        qa[ks][2] = *(const uint32_t*)(qp + (size_t)gID * D3 + 16 * ks + 2 * tg + 8);
        qa[ks][3] = *(const uint32_t*)(qp + (size_t)(gID + 8) * D3 + 16 * ks + 2 * tg + 8);
    }

    const uint32_t k_lane_off = (uint32_t)((((grp >> 1) * 8 + rowl) * KPH + (grp & 1) * 8) * 2);
    const uint32_t v_lane_off = (uint32_t)((((grp & 1) * 8 + rowl) * KPH + (grp >> 1) * 8) * 2);

    float o[8][4];
    #pragma unroll
    for (int n = 0; n < 8; n++)
        #pragma unroll
        for (int j = 0; j < 4; j++) o[n][j] = 0.f;
    float m0 = -1e30f, m1 = -1e30f, l0 = 0.f, l1 = 0.f;
    const float CS = QSCALE_LOG2E;

    // prologue: tiles 0,1
    #pragma unroll
    for (int pi = 0; pi < 2; pi++) {
        const int r0 = pi * 64;
        #pragma unroll
        for (int j = 0; j < 2; j++) {
            const int idx = tid + j * 256;
            const int r = idx >> 3, c = idx & 7;
            CP_ASYNC16(kB[pi] + (uint32_t)(r * KPH + c * 8) * 2u,
                       kbase + (size_t)(r0 + r) * D3 + c * 8);
            CP_ASYNC16(vB[pi] + (uint32_t)(r * KPH + c * 8) * 2u,
                       vbase + (size_t)(r0 + r) * D3 + c * 8);
        }
        CP_COMMIT();
    }

    for (int i = 0; i < 32; i++) {
        const int s = i & 1;
        if (i < 31) { CP_WAIT1(); } else { CP_WAIT0(); }
        __syncthreads();

        // ---- S = Q @ K^T ----
        float sa[8][4];
        #pragma unroll
        for (int n = 0; n < 8; n++)
            #pragma unroll
            for (int j = 0; j < 4; j++) sa[n][j] = 0.f;
        #pragma unroll
        for (int ks = 0; ks < 4; ks++) {
            #pragma unroll
            for (int np = 0; np < 4; np++) {
                uint32_t r0, r1, r2, r3;
                LDSM_X4(r0, r1, r2, r3,
                        kB[s] + k_lane_off + (uint32_t)((np * 16 * KPH + ks * 16) * 2));
                mma_f16(sa[2*np][0], sa[2*np][1], sa[2*np][2], sa[2*np][3],
                        qa[ks][0], qa[ks][1], qa[ks][2], qa[ks][3], r0, r1);
                mma_f16(sa[2*np+1][0], sa[2*np+1][1], sa[2*np+1][2], sa[2*np+1][3],
                        qa[ks][0], qa[ks][1], qa[ks][2], qa[ks][3], r2, r3);
            }
        }

        // ---- online softmax (base 2, scale via fma; P packed to half2) ----
        float rmax0 = sa[0][0], rmax1 = sa[0][2];
        #pragma unroll
        for (int n = 0; n < 8; n++) {
            rmax0 = fmaxf(rmax0, fmaxf(sa[n][0], sa[n][1]));
            rmax1 = fmaxf(rmax1, fmaxf(sa[n][2], sa[n][3]));
        }
        rmax0 = fmaxf(rmax0, __shfl_xor_sync(0xffffffffu, rmax0, 1));
        rmax0 = fmaxf(rmax0, __shfl_xor_sync(0xffffffffu, rmax0, 2));
        rmax1 = fmaxf(rmax1, __shfl_xor_sync(0xffffffffu, rmax1, 1));
        rmax1 = fmaxf(rmax1, __shfl_xor_sync(0xffffffffu, rmax1, 2));
        const float nm0 = fmaxf(m0, rmax0 * CS), nm1 = fmaxf(m1, rmax1 * CS);
        const float c0 = ex2f(m0 - nm0), c1 = ex2f(m1 - nm1);
        m0 = nm0; m1 = nm1;
        float s0 = 0.f, s1 = 0.f;
        uint32_t p01[8], p23[8];
        #pragma unroll
        for (int n = 0; n < 8; n++) {
            const float p0 = ex2f(fmaf(sa[n][0], CS, -m0));
            const float p1 = ex2f(fmaf(sa[n][1], CS, -m0));
            const float p2 = ex2f(fmaf(sa[n][2], CS, -m1));
            const float p3 = ex2f(fmaf(sa[n][3], CS, -m1));
            s0 += p0 + p1; s1 += p2 + p3;
            p01[n] = packh2(p0, p1);
            p23[n] = packh2(p2, p3);
            o[n][0] *= c0; o[n][1] *= c0; o[n][2] *= c1; o[n][3] *= c1;
        }
        s0 += __shfl_xor_sync(0xffffffffu, s0, 1);
        s0 += __shfl_xor_sync(0xffffffffu, s0, 2);
        s1 += __shfl_xor_sync(0xffffffffu, s1, 1);
        s1 += __shfl_xor_sync(0xffffffffu, s1, 2);
        l0 = l0 * c0 + s0;
        l1 = l1 * c1 + s1;

        // ---- O += P @ V (ldmatrix.trans V fragments) ----
        #pragma unroll
        for (int kc = 0; kc < 4; kc++) {
            const uint32_t a0 = p01[2*kc], a1 = p23[2*kc];
            const uint32_t a2 = p01[2*kc+1], a3 = p23[2*kc+1];
            #pragma unroll
            for (int cp = 0; cp < 4; cp++) {
                uint32_t r0, r1, r2, r3;
                LDSM_X4_T(r0, r1, r2, r3,
                          vB[s] + v_lane_off + (uint32_t)((kc * 16 * KPH + cp * 16) * 2));
                mma_f16(o[2*cp][0], o[2*cp][1], o[2*cp][2], o[2*cp][3],
                        a0, a1, a2, a3, r0, r1);
                mma_f16(o[2*cp+1][0], o[2*cp+1][1], o[2*cp+1][2], o[2*cp+1][3],
                        a0, a1, a2, a3, r2, r3);
            }
        }
        __syncthreads();

        if (i + 2 < 32) {
            const int r0 = (i + 2) * 64;
            #pragma unroll
            for (int j = 0; j < 2; j++) {
                const int idx = tid + j * 256;
                const int r = idx >> 3, c = idx & 7;
                CP_ASYNC16(kB[s] + (uint32_t)(r * KPH + c * 8) * 2u,
                           kbase + (size_t)(r0 + r) * D3 + c * 8);
                CP_ASYNC16(vB[s] + (uint32_t)(r * KPH + c * 8) * 2u,
                           vbase + (size_t)(r0 + r) * D3 + c * 8);
            }
            CP_COMMIT();
        }
    }

    // epilogue: normalize, write fp16 half2 pairs
    const float inv0 = 1.f / l0, inv1 = 1.f / l1;
    const size_t grow = (size_t)(bb * S + qbase + gID);
    #pragma unroll
    for (int n = 0; n < 8; n++) {
        const int col = h * DH + n * 8 + 2 * tg;
        ctxh[(grow * INNER + col) >> 1] =
            packh2(o[n][0] * inv0, o[n][1] * inv0);
        ctxh[((grow + 8) * INNER + col) >> 1] =
            packh2(o[n][2] * inv1, o[n][3] * inv1);
    }
}

// ---------------------------------------------------------------------------
extern "C" void kernel_launch(void* const* d_in, const int* in_sizes, int n_in,
                              void* d_out, int out_size)
{
    const float* x        = (const float*)d_in[0];
    const float* ln_gamma = (const float*)d_in[1];
    const float* ln_beta  = (const float*)d_in[2];
    const float* w_qkv    = (const float*)d_in[3];
    const float* w_out    = (const float*)d_in[4];
    const float* b_out    = (const float*)d_in[5];
    float* out = (float*)d_out;

    void* sp = nullptr;
    cudaGetSymbolAddress(&sp, g_scratch);
    float* base = (float*)sp;
    uint32_t* xnh  = (uint32_t*)base;                        // ROWS*D halves
    uint32_t* qkvh = xnh + (size_t)ROWS * D / 2;             // ROWS*D3 halves
    uint32_t* ctxh = qkvh + (size_t)ROWS * D3 / 2;           // ROWS*D halves
    __half*   wqT  = (__half*)(ctxh + (size_t)ROWS * D / 2); // [D3][D] halves
    __half*   woT  = wqT + (size_t)D3 * D;                   // [D][D] halves

    cudaFuncSetAttribute(gemm_h_kernel, cudaFuncAttributeMaxDynamicSharedMemorySize, GEMM_SMEM);
    cudaFuncSetAttribute(attn_kernel, cudaFuncAttributeMaxDynamicSharedMemorySize, ATTN_SMEM);

    // transpose + pack weights to fp16 [N][K]
    pack_wT_kernel<<<dim3(D3 / 32, D / 32), dim3(32, 8)>>>(w_qkv, wqT, D3);
    pack_wT_kernel<<<dim3(D / 32, D / 32), dim3(32, 8)>>>(w_out, woT, D);

    // 1. LayerNorm (fp16 output)
    ln_kernel<<<ROWS, 256>>>(x, ln_gamma, ln_beta, xnh);

    // 2. QKV projection (fp16 tensor cores + ldmatrix, BK=64, fp16 output)
    gemm_h_kernel<<<dim3(D3 / 128, ROWS / 128), 256, GEMM_SMEM>>>(
        (const __half*)xnh, wqT, nullptr, nullptr, qkvh, D3);

    // 3. Flash attention (fp16 tensor cores + ldmatrix, fp16 ctx output)
    attn_kernel<<<dim3(S / 128, HEADS, B), 256, ATTN_SMEM>>>(
        (const __half*)qkvh, ctxh);

    // 4. Output projection + bias (fp16 tensor cores + ldmatrix, fp32 out)
    gemm_h_kernel<<<dim3(D / 128, ROWS / 128), 256, GEMM_SMEM>>>(
        (const __half*)ctxh, woT, b_out, out, nullptr, D);
}

// round 14
// speedup vs baseline: 1.5631x; 1.5631x over previous
#include <cuda_runtime.h>
#include <cuda_fp16.h>
#include <cstdint>
#include <math.h>

// Problem constants
#define B       2
#define S       2048
#define D       1024
#define HEADS   16
#define DH      64
#define INNER   1024
#define D3      3072
#define ROWS    4096
#define LN_EPS  1e-5f
// 0.125 * log2(e): applied to S inside softmax (fma), Q stays raw fp16
#define QSCALE_LOG2E 0.18033688011112042f

// Scratch: xn(half) | qkv(half) | ctx(half) | w_qkv^T(half) | w_out^T(half)
__device__ float g_scratch[(size_t)ROWS * D + (size_t)ROWS * D3 + (size_t)ROWS * D
                           + (size_t)D * D3 + (size_t)D * D];

// ---------------------------------------------------------------------------
// Helpers
// ---------------------------------------------------------------------------
__device__ __forceinline__ uint32_t smem_u32(const void* p) {
    uint32_t a;
    asm("{ .reg .u64 t; cvta.to.shared.u64 t, %1; cvt.u32.u64 %0, t; }" : "=r"(a) : "l"(p));
    return a;
}
__device__ __forceinline__ float ex2f(float x) {
    float r;
    asm("ex2.approx.ftz.f32 %0, %1;" : "=f"(r) : "f"(x));
    return r;
}
__device__ __forceinline__ uint32_t packh2(float lo, float hi) {
    __half2 h = __floats2half2_rn(lo, hi);
    return *(uint32_t*)&h;
}

#define CP_ASYNC16(dst, src) \
    asm volatile("cp.async.cg.shared.global [%0], [%1], 16;" :: "r"(dst), "l"(src))
#define CP_COMMIT()  asm volatile("cp.async.commit_group;" ::: "memory")
#define CP_WAIT2()   asm volatile("cp.async.wait_group 2;" ::: "memory")
#define CP_WAIT1()   asm volatile("cp.async.wait_group 1;" ::: "memory")
#define CP_WAIT0()   asm volatile("cp.async.wait_group 0;" ::: "memory")

__device__ __forceinline__ void mma_f16(
    float& d0, float& d1, float& d2, float& d3,
    uint32_t a0, uint32_t a1, uint32_t a2, uint32_t a3,
    uint32_t b0, uint32_t b1)
{
    asm volatile(
        "mma.sync.aligned.m16n8k16.row.col.f32.f16.f16.f32 "
        "{%0,%1,%2,%3}, {%4,%5,%6,%7}, {%8,%9}, {%0,%1,%2,%3};"
        : "+f"(d0), "+f"(d1), "+f"(d2), "+f"(d3)
        : "r"(a0), "r"(a1), "r"(a2), "r"(a3), "r"(b0), "r"(b1));
}
#define LDSM_X4(r0, r1, r2, r3, addr) \
    asm volatile("ldmatrix.sync.aligned.m8n8.x4.shared.b16 {%0,%1,%2,%3}, [%4];" \
        : "=r"(r0), "=r"(r1), "=r"(r2), "=r"(r3) : "r"(addr))
#define LDSM_X4_T(r0, r1, r2, r3, addr) \
    asm volatile("ldmatrix.sync.aligned.m8n8.x4.trans.shared.b16 {%0,%1,%2,%3}, [%4];" \
        : "=r"(r0), "=r"(r1), "=r"(r2), "=r"(r3) : "r"(addr))

// ---------------------------------------------------------------------------
// LayerNorm (output written as fp16, rn)
// ---------------------------------------------------------------------------
__global__ __launch_bounds__(256) void ln_kernel(
    const float* __restrict__ x, const float* __restrict__ gamma,
    const float* __restrict__ beta, uint32_t* __restrict__ y)
{
    const int row = blockIdx.x;
    const int t = threadIdx.x;
    const float4* xp = (const float4*)(x + (size_t)row * D);
    float4 v = xp[t];
    float s  = v.x + v.y + v.z + v.w;
    float ss = v.x * v.x + v.y * v.y + v.z * v.z + v.w * v.w;
    #pragma unroll
    for (int off = 16; off > 0; off >>= 1) {
        s  += __shfl_down_sync(0xffffffffu, s,  off);
        ss += __shfl_down_sync(0xffffffffu, ss, off);
    }
    __shared__ float sh_s[8], sh_ss[8];
    const int w = t >> 5, lane = t & 31;
    if (lane == 0) { sh_s[w] = s; sh_ss[w] = ss; }
    __syncthreads();
    __shared__ float mu_sh, rstd_sh;
    if (t == 0) {
        float S0 = 0.f, SS0 = 0.f;
        #pragma unroll
        for (int i = 0; i < 8; i++) { S0 += sh_s[i]; SS0 += sh_ss[i]; }
        const float mu  = S0 * (1.0f / D);
        const float var = SS0 * (1.0f / D) - mu * mu;
        mu_sh = mu;
        rstd_sh = rsqrtf(var + LN_EPS);
    }
    __syncthreads();
    const float mu = mu_sh, rstd = rstd_sh;
    float4 g  = ((const float4*)gamma)[t];
    float4 bb = ((const float4*)beta)[t];
    const float ox = (v.x - mu) * rstd * g.x + bb.x;
    const float oy = (v.y - mu) * rstd * g.y + bb.y;
    const float oz = (v.z - mu) * rstd * g.z + bb.z;
    const float ow = (v.w - mu) * rstd * g.w + bb.w;
    ((uint2*)(y + (size_t)row * (D / 2)))[t] = make_uint2(packh2(ox, oy), packh2(oz, ow));
}

// ---------------------------------------------------------------------------
// Pack + transpose weights: W[K=1024][N] f32 -> WT[N][K=1024] fp16.
// grid (N/32, 32), block (32, 8)
// ---------------------------------------------------------------------------
__global__ __launch_bounds__(256) void pack_wT_kernel(
    const float* __restrict__ W, __half* __restrict__ WT, int N)
{
    __shared__ float tile[32][33];
    const int n0 = blockIdx.x * 32, k0 = blockIdx.y * 32;
    const int tx = threadIdx.x, ty = threadIdx.y;
    #pragma unroll
    for (int j = 0; j < 32; j += 8)
        tile[ty + j][tx] = W[(size_t)(k0 + ty + j) * N + n0 + tx];
    __syncthreads();
    #pragma unroll
    for (int j = 0; j < 32; j += 8)
        WT[(size_t)(n0 + ty + j) * D + k0 + tx] = __float2half_rn(tile[tx][ty + j]);
}

// ---------------------------------------------------------------------------
// FP16 mma.sync GEMM with ldmatrix fragments, BK=32, 4-STAGE cp.async:
// C = A[M,1024] @ WT[N,1024]^T (+bias), f32 accumulate.
// 128x128 tile, 256 threads, 8 warps (warp-tile 32x64).
// One __syncthreads per chunk; wait_group 2 with unconditional commits
// (possibly empty) so the "newest 2 groups" invariant holds at the tail.
// smem pitch 40 halves (R12-proven conflict-free). 80KB smem -> 2 CTAs/SM.
// Output: fp32 (Cf) or packed fp16 (Ch).
// ---------------------------------------------------------------------------
#define GP 40
#define G_ST (128 * GP)                    // halves per operand per stage
#define GEMM_SMEM (4 * 2 * G_ST * 2)       // 81920 B

__device__ __forceinline__ void gm_load_chunk(
    uint32_t aS, uint32_t bS,
    const __half* __restrict__ A, const __half* __restrict__ WT,
    int bm, int bn, int k0, int tid)
{
    #pragma unroll
    for (int j = 0; j < 2; j++) {
        const int idx = tid + j * 256;
        const int r = idx >> 2, c = idx & 3;
        CP_ASYNC16(aS + (uint32_t)(r * GP + c * 8) * 2u,
                   A + (size_t)(bm + r) * D + k0 + c * 8);
        CP_ASYNC16(bS + (uint32_t)(r * GP + c * 8) * 2u,
                   WT + (size_t)(bn + r) * D + k0 + c * 8);
    }
}

__global__ __launch_bounds__(256, 2) void gemm_h_kernel(
    const __half* __restrict__ A, const __half* __restrict__ WT,
    const float* __restrict__ bias, float* __restrict__ Cf,
    uint32_t* __restrict__ Ch, int N)
{
    extern __shared__ char smc[];
    const uint32_t base = smem_u32(smc);
    uint32_t aB[4], bB[4];
    #pragma unroll
    for (int s = 0; s < 4; s++) {
        aB[s] = base + (uint32_t)s * (G_ST * 2);
        bB[s] = base + 4u * (G_ST * 2) + (uint32_t)s * (G_ST * 2);
    }

    const int tid = threadIdx.x;
    const int wid = tid >> 5, lane = tid & 31;
    const int gID = lane >> 2, tg = lane & 3;
    const int rowl = lane & 7, grp = lane >> 3;
    const int bm = blockIdx.y * 128, bn = blockIdx.x * 128;
    const int wm = (wid & 3) * 32, wn = (wid >> 2) * 64;

    // ldmatrix lane offsets (halves)
    const uint32_t aOff = (uint32_t)(((grp & 1) * 8 + rowl) * GP + (grp >> 1) * 8);
    const uint32_t bOff = (uint32_t)(((grp >> 1) * 8 + rowl) * GP + (grp & 1) * 8);

    float acc[2][8][4];
    #pragma unroll
    for (int im = 0; im < 2; im++)
        #pragma unroll
        for (int n = 0; n < 8; n++)
            #pragma unroll
            for (int j = 0; j < 4; j++) acc[im][n][j] = 0.f;

    // prologue: chunks 0,1,2 -> stages 0,1,2
    #pragma unroll
    for (int pi = 0; pi < 3; pi++) {
        gm_load_chunk(aB[pi], bB[pi], A, WT, bm, bn, pi * 32, tid);
        CP_COMMIT();
    }

    #pragma unroll 4
    for (int i = 0; i < 32; i++) {
        const int s = i & 3;
        CP_WAIT2();
        __syncthreads();
        if (i + 3 < 32)
            gm_load_chunk(aB[(i + 3) & 3], bB[(i + 3) & 3], A, WT, bm, bn,
                          (i + 3) * 32, tid);
        CP_COMMIT();   // unconditional: keeps group-age invariant at tail

        const uint32_t aS = aB[s], bS = bB[s];
        #pragma unroll
        for (int ks = 0; ks < 2; ks++) {
            uint32_t af[2][4];
            #pragma unroll
            for (int im = 0; im < 2; im++)
                LDSM_X4(af[im][0], af[im][1], af[im][2], af[im][3],
                        aS + (aOff + (uint32_t)((wm + im * 16) * GP + ks * 16)) * 2u);
            #pragma unroll
            for (int np = 0; np < 4; np++) {
                uint32_t b0, b1, b2, b3;
                LDSM_X4(b0, b1, b2, b3,
                        bS + (bOff + (uint32_t)((wn + np * 16) * GP + ks * 16)) * 2u);
                #pragma unroll
                for (int im = 0; im < 2; im++) {
                    mma_f16(acc[im][2*np][0], acc[im][2*np][1],
                            acc[im][2*np][2], acc[im][2*np][3],
                            af[im][0], af[im][1], af[im][2], af[im][3], b0, b1);
                    mma_f16(acc[im][2*np+1][0], acc[im][2*np+1][1],
                            acc[im][2*np+1][2], acc[im][2*np+1][3],
                            af[im][0], af[im][1], af[im][2], af[im][3], b2, b3);
                }
            }
        }
    }

    // epilogue (acc: rows gID,gID+8; cols 2tg,2tg+1 within each n*8 group)
    #pragma unroll
    for (int im = 0; im < 2; im++) {
        const int r0 = bm + wm + im * 16 + gID;
        #pragma unroll
        for (int n = 0; n < 8; n++) {
            const int col = bn + wn + n * 8 + 2 * tg;
            float v0 = acc[im][n][0], v1 = acc[im][n][1];
            float v2 = acc[im][n][2], v3 = acc[im][n][3];
            if (bias) {
                const float b0 = bias[col], b1 = bias[col + 1];
                v0 += b0; v1 += b1; v2 += b0; v3 += b1;
            }
            if (Ch) {
                Ch[((size_t)r0 * N + col) >> 1]       = packh2(v0, v1);
                Ch[((size_t)(r0 + 8) * N + col) >> 1] = packh2(v2, v3);
            } else {
                *(float2*)&Cf[(size_t)r0 * N + col]       = make_float2(v0, v1);
                *(float2*)&Cf[(size_t)(r0 + 8) * N + col] = make_float2(v2, v3);
            }
        }
    }
}

// ---------------------------------------------------------------------------
// FP16 mma.sync flash attention (R11-good version, unchanged).
// ---------------------------------------------------------------------------
#define KPH 72
#define KV_TILE_B (64 * KPH * 2)            // 9216 B per K or V stage
#define ATTN_SMEM (2 * 2 * KV_TILE_B)       // 36864 B

__global__ __launch_bounds__(256, 2) void attn_kernel(
    const __half* __restrict__ qkv, uint32_t* __restrict__ ctxh)
{
    extern __shared__ char smc[];
    const uint32_t kB[2] = { smem_u32(smc),                 smem_u32(smc) + KV_TILE_B };
    const uint32_t vB[2] = { kB[0] + 2 * KV_TILE_B,         kB[1] + 2 * KV_TILE_B };

    const int tid = threadIdx.x;
    const int wid = tid >> 5, lane = tid & 31;
    const int gID = lane >> 2, tg = lane & 3;
    const int rowl = lane & 7, grp = lane >> 3;
    const int h = blockIdx.y, bb = blockIdx.z;
    const int qbase = blockIdx.x * 128 + wid * 16;

    const __half* qp = qkv + (size_t)(bb * S + qbase) * D3 + h * DH;
    const __half* kbase = qkv + (size_t)bb * S * D3 + INNER + h * DH;
    const __half* vbase = kbase + INNER;

    // Q fragments: raw fp16, u32 pair slots
    uint32_t qa[4][4];
    #pragma unroll
    for (int ks = 0; ks < 4; ks++) {
        qa[ks][0] = *(const uint32_t*)(qp + (size_t)gID * D3 + 16 * ks + 2 * tg);
        qa[ks][1] = *(const uint32_t*)(qp + (size_t)(gID + 8) * D3 + 16 * ks + 2 * tg);
        qa[ks][2] = *(const uint32_t*)(qp + (size_t)gID * D3 + 16 * ks + 2 * tg + 8);
        qa[ks][3] = *(const uint32_t*)(qp + (size_t)(gID + 8) * D3 + 16 * ks + 2 * tg + 8);
    }

    const uint32_t k_lane_off = (uint32_t)((((grp >> 1) * 8 + rowl) * KPH + (grp & 1) * 8) * 2);
    const uint32_t v_lane_off = (uint32_t)((((grp & 1) * 8 + rowl) * KPH + (grp >> 1) * 8) * 2);

    float o[8][4];
    #pragma unroll
    for (int n = 0; n < 8; n++)
        #pragma unroll
        for (int j = 0; j < 4; j++) o[n][j] = 0.f;
    float m0 = -1e30f, m1 = -1e30f, l0 = 0.f, l1 = 0.f;
    const float CS = QSCALE_LOG2E;

    // prologue: tiles 0,1
    #pragma unroll
    for (int pi = 0; pi < 2; pi++) {
        const int r0 = pi * 64;
        #pragma unroll
        for (int j = 0; j < 2; j++) {
            const int idx = tid + j * 256;
            const int r = idx >> 3, c = idx & 7;
            CP_ASYNC16(kB[pi] + (uint32_t)(r * KPH + c * 8) * 2u,
                       kbase + (size_t)(r0 + r) * D3 + c * 8);
            CP_ASYNC16(vB[pi] + (uint32_t)(r * KPH + c * 8) * 2u,
                       vbase + (size_t)(r0 + r) * D3 + c * 8);
        }
        CP_COMMIT();
    }

    for (int i = 0; i < 32; i++) {
        const int s = i & 1;
        if (i < 31) { CP_WAIT1(); } else { CP_WAIT0(); }
        __syncthreads();

        // ---- S = Q @ K^T ----
        float sa[8][4];
        #pragma unroll
        for (int n = 0; n < 8; n++)
            #pragma unroll
            for (int j = 0; j < 4; j++) sa[n][j] = 0.f;
        #pragma unroll
        for (int ks = 0; ks < 4; ks++) {
            #pragma unroll
            for (int np = 0; np < 4; np++) {
                uint32_t r0, r1, r2, r3;
                LDSM_X4(r0, r1, r2, r3,
                        kB[s] + k_lane_off + (uint32_t)((np * 16 * KPH + ks * 16) * 2));
                mma_f16(sa[2*np][0], sa[2*np][1], sa[2*np][2], sa[2*np][3],
                        qa[ks][0], qa[ks][1], qa[ks][2], qa[ks][3], r0, r1);
                mma_f16(sa[2*np+1][0], sa[2*np+1][1], sa[2*np+1][2], sa[2*np+1][3],
                        qa[ks][0], qa[ks][1], qa[ks][2], qa[ks][3], r2, r3);
            }
        }

        // ---- online softmax (base 2, scale via fma; P packed to half2) ----
        float rmax0 = sa[0][0], rmax1 = sa[0][2];
        #pragma unroll
        for (int n = 0; n < 8; n++) {
            rmax0 = fmaxf(rmax0, fmaxf(sa[n][0], sa[n][1]));
            rmax1 = fmaxf(rmax1, fmaxf(sa[n][2], sa[n][3]));
        }
        rmax0 = fmaxf(rmax0, __shfl_xor_sync(0xffffffffu, rmax0, 1));
        rmax0 = fmaxf(rmax0, __shfl_xor_sync(0xffffffffu, rmax0, 2));
        rmax1 = fmaxf(rmax1, __shfl_xor_sync(0xffffffffu, rmax1, 1));
        rmax1 = fmaxf(rmax1, __shfl_xor_sync(0xffffffffu, rmax1, 2));
        const float nm0 = fmaxf(m0, rmax0 * CS), nm1 = fmaxf(m1, rmax1 * CS);
        const float c0 = ex2f(m0 - nm0), c1 = ex2f(m1 - nm1);
        m0 = nm0; m1 = nm1;
        float s0 = 0.f, s1 = 0.f;
        uint32_t p01[8], p23[8];
        #pragma unroll
        for (int n = 0; n < 8; n++) {
            const float p0 = ex2f(fmaf(sa[n][0], CS, -m0));
            const float p1 = ex2f(fmaf(sa[n][1], CS, -m0));
            const float p2 = ex2f(fmaf(sa[n][2], CS, -m1));
            const float p3 = ex2f(fmaf(sa[n][3], CS, -m1));
            s0 += p0 + p1; s1 += p2 + p3;
            p01[n] = packh2(p0, p1);
            p23[n] = packh2(p2, p3);
            o[n][0] *= c0; o[n][1] *= c0; o[n][2] *= c1; o[n][3] *= c1;
        }
        s0 += __shfl_xor_sync(0xffffffffu, s0, 1);
        s0 += __shfl_xor_sync(0xffffffffu, s0, 2);
        s1 += __shfl_xor_sync(0xffffffffu, s1, 1);
        s1 += __shfl_xor_sync(0xffffffffu, s1, 2);
        l0 = l0 * c0 + s0;
        l1 = l1 * c1 + s1;

        // ---- O += P @ V (ldmatrix.trans V fragments) ----
        #pragma unroll
        for (int kc = 0; kc < 4; kc++) {
            const uint32_t a0 = p01[2*kc], a1 = p23[2*kc];
            const uint32_t a2 = p01[2*kc+1], a3 = p23[2*kc+1];
            #pragma unroll
            for (int cp = 0; cp < 4; cp++) {
                uint32_t r0, r1, r2, r3;
                LDSM_X4_T(r0, r1, r2, r3,
                          vB[s] + v_lane_off + (uint32_t)((kc * 16 * KPH + cp * 16) * 2));
                mma_f16(o[2*cp][0], o[2*cp][1], o[2*cp][2], o[2*cp][3],
                        a0, a1, a2, a3, r0, r1);
                mma_f16(o[2*cp+1][0], o[2*cp+1][1], o[2*cp+1][2], o[2*cp+1][3],
                        a0, a1, a2, a3, r2, r3);
            }
        }
        __syncthreads();

        if (i + 2 < 32) {
            const int r0 = (i + 2) * 64;
            #pragma unroll
            for (int j = 0; j < 2; j++) {
                const int idx = tid + j * 256;
                const int r = idx >> 3, c = idx & 7;
                CP_ASYNC16(kB[s] + (uint32_t)(r * KPH + c * 8) * 2u,
                           kbase + (size_t)(r0 + r) * D3 + c * 8);
                CP_ASYNC16(vB[s] + (uint32_t)(r * KPH + c * 8) * 2u,
                           vbase + (size_t)(r0 + r) * D3 + c * 8);
            }
            CP_COMMIT();
        }
    }

    // epilogue: normalize, write fp16 half2 pairs
    const float inv0 = 1.f / l0, inv1 = 1.f / l1;
    const size_t grow = (size_t)(bb * S + qbase + gID);
    #pragma unroll
    for (int n = 0; n < 8; n++) {
        const int col = h * DH + n * 8 + 2 * tg;
        ctxh[(grow * INNER + col) >> 1] =
            packh2(o[n][0] * inv0, o[n][1] * inv0);
        ctxh[((grow + 8) * INNER + col) >> 1] =
            packh2(o[n][2] * inv1, o[n][3] * inv1);
    }
}

// ---------------------------------------------------------------------------
extern "C" void kernel_launch(void* const* d_in, const int* in_sizes, int n_in,
                              void* d_out, int out_size)
{
    const float* x        = (const float*)d_in[0];
    const float* ln_gamma = (const float*)d_in[1];
    const float* ln_beta  = (const float*)d_in[2];
    const float* w_qkv    = (const float*)d_in[3];
    const float* w_out    = (const float*)d_in[4];
    const float* b_out    = (const float*)d_in[5];
    float* out = (float*)d_out;

    void* sp = nullptr;
    cudaGetSymbolAddress(&sp, g_scratch);
    float* base = (float*)sp;
    uint32_t* xnh  = (uint32_t*)base;                        // ROWS*D halves
    uint32_t* qkvh = xnh + (size_t)ROWS * D / 2;             // ROWS*D3 halves
    uint32_t* ctxh = qkvh + (size_t)ROWS * D3 / 2;           // ROWS*D halves
    __half*   wqT  = (__half*)(ctxh + (size_t)ROWS * D / 2); // [D3][D] halves
    __half*   woT  = wqT + (size_t)D3 * D;                   // [D][D] halves

    cudaFuncSetAttribute(gemm_h_kernel, cudaFuncAttributeMaxDynamicSharedMemorySize, GEMM_SMEM);
    cudaFuncSetAttribute(attn_kernel, cudaFuncAttributeMaxDynamicSharedMemorySize, ATTN_SMEM);

    // transpose + pack weights to fp16 [N][K]
    pack_wT_kernel<<<dim3(D3 / 32, D / 32), dim3(32, 8)>>>(w_qkv, wqT, D3);
    pack_wT_kernel<<<dim3(D / 32, D / 32), dim3(32, 8)>>>(w_out, woT, D);

    // 1. LayerNorm (fp16 output)
    ln_kernel<<<ROWS, 256>>>(x, ln_gamma, ln_beta, xnh);

    // 2. QKV projection (fp16 tensor cores + ldmatrix, 4-stage, fp16 output)
    gemm_h_kernel<<<dim3(D3 / 128, ROWS / 128), 256, GEMM_SMEM>>>(
        (const __half*)xnh, wqT, nullptr, nullptr, qkvh, D3);

    // 3. Flash attention (fp16 tensor cores + ldmatrix, fp16 ctx output)
    attn_kernel<<<dim3(S / 128, HEADS, B), 256, ATTN_SMEM>>>(
        (const __half*)qkvh, ctxh);

    // 4. Output projection + bias (fp16 tensor cores + ldmatrix, fp32 out)
    gemm_h_kernel<<<dim3(D / 128, ROWS / 128), 256, GEMM_SMEM>>>(
        (const __half*)ctxh, woT, b_out, out, nullptr, D);
}

// round 15
// speedup vs baseline: 1.5924x; 1.0188x over previous
#include <cuda_runtime.h>
#include <cuda_fp16.h>
#include <cstdint>
#include <math.h>

// Problem constants
#define B       2
#define S       2048
#define D       1024
#define HEADS   16
#define DH      64
#define INNER   1024
#define D3      3072
#define ROWS    4096
#define LN_EPS  1e-5f
// 0.125 * log2(e): applied to S inside softmax (fma), Q stays raw fp16
#define QSCALE_LOG2E 0.18033688011112042f

// Scratch: xn(half) | qkv(half) | ctx(half) | w_qkv^T(half) | w_out^T(half)
__device__ float g_scratch[(size_t)ROWS * D + (size_t)ROWS * D3 + (size_t)ROWS * D
                           + (size_t)D * D3 + (size_t)D * D];

// ---------------------------------------------------------------------------
// Helpers
// ---------------------------------------------------------------------------
__device__ __forceinline__ uint32_t smem_u32(const void* p) {
    uint32_t a;
    asm("{ .reg .u64 t; cvta.to.shared.u64 t, %1; cvt.u32.u64 %0, t; }" : "=r"(a) : "l"(p));
    return a;
}
__device__ __forceinline__ float ex2f(float x) {
    float r;
    asm("ex2.approx.ftz.f32 %0, %1;" : "=f"(r) : "f"(x));
    return r;
}
__device__ __forceinline__ uint32_t packh2(float lo, float hi) {
    __half2 h = __floats2half2_rn(lo, hi);
    return *(uint32_t*)&h;
}

#define CP_ASYNC16(dst, src) \
    asm volatile("cp.async.cg.shared.global [%0], [%1], 16;" :: "r"(dst), "l"(src))
#define CP_COMMIT()  asm volatile("cp.async.commit_group;" ::: "memory")
#define CP_WAIT2()   asm volatile("cp.async.wait_group 2;" ::: "memory")

__device__ __forceinline__ void mma_f16(
    float& d0, float& d1, float& d2, float& d3,
    uint32_t a0, uint32_t a1, uint32_t a2, uint32_t a3,
    uint32_t b0, uint32_t b1)
{
    asm volatile(
        "mma.sync.aligned.m16n8k16.row.col.f32.f16.f16.f32 "
        "{%0,%1,%2,%3}, {%4,%5,%6,%7}, {%8,%9}, {%0,%1,%2,%3};"
        : "+f"(d0), "+f"(d1), "+f"(d2), "+f"(d3)
        : "r"(a0), "r"(a1), "r"(a2), "r"(a3), "r"(b0), "r"(b1));
}
#define LDSM_X4(r0, r1, r2, r3, addr) \
    asm volatile("ldmatrix.sync.aligned.m8n8.x4.shared.b16 {%0,%1,%2,%3}, [%4];" \
        : "=r"(r0), "=r"(r1), "=r"(r2), "=r"(r3) : "r"(addr))
#define LDSM_X4_T(r0, r1, r2, r3, addr) \
    asm volatile("ldmatrix.sync.aligned.m8n8.x4.trans.shared.b16 {%0,%1,%2,%3}, [%4];" \
        : "=r"(r0), "=r"(r1), "=r"(r2), "=r"(r3) : "r"(addr))

// ---------------------------------------------------------------------------
// LayerNorm (output written as fp16, rn)
// ---------------------------------------------------------------------------
__global__ __launch_bounds__(256) void ln_kernel(
    const float* __restrict__ x, const float* __restrict__ gamma,
    const float* __restrict__ beta, uint32_t* __restrict__ y)
{
    const int row = blockIdx.x;
    const int t = threadIdx.x;
    const float4* xp = (const float4*)(x + (size_t)row * D);
    float4 v = xp[t];
    float s  = v.x + v.y + v.z + v.w;
    float ss = v.x * v.x + v.y * v.y + v.z * v.z + v.w * v.w;
    #pragma unroll
    for (int off = 16; off > 0; off >>= 1) {
        s  += __shfl_down_sync(0xffffffffu, s,  off);
        ss += __shfl_down_sync(0xffffffffu, ss, off);
    }
    __shared__ float sh_s[8], sh_ss[8];
    const int w = t >> 5, lane = t & 31;
    if (lane == 0) { sh_s[w] = s; sh_ss[w] = ss; }
    __syncthreads();
    __shared__ float mu_sh, rstd_sh;
    if (t == 0) {
        float S0 = 0.f, SS0 = 0.f;
        #pragma unroll
        for (int i = 0; i < 8; i++) { S0 += sh_s[i]; SS0 += sh_ss[i]; }
        const float mu  = S0 * (1.0f / D);
        const float var = SS0 * (1.0f / D) - mu * mu;
        mu_sh = mu;
        rstd_sh = rsqrtf(var + LN_EPS);
    }
    __syncthreads();
    const float mu = mu_sh, rstd = rstd_sh;
    float4 g  = ((const float4*)gamma)[t];
    float4 bb = ((const float4*)beta)[t];
    const float ox = (v.x - mu) * rstd * g.x + bb.x;
    const float oy = (v.y - mu) * rstd * g.y + bb.y;
    const float oz = (v.z - mu) * rstd * g.z + bb.z;
    const float ow = (v.w - mu) * rstd * g.w + bb.w;
    ((uint2*)(y + (size_t)row * (D / 2)))[t] = make_uint2(packh2(ox, oy), packh2(oz, ow));
}

// ---------------------------------------------------------------------------
// Pack + transpose weights: W[K=1024][N] f32 -> WT[N][K=1024] fp16.
// grid (N/32, 32), block (32, 8)
// ---------------------------------------------------------------------------
__global__ __launch_bounds__(256) void pack_wT_kernel(
    const float* __restrict__ W, __half* __restrict__ WT, int N)
{
    __shared__ float tile[32][33];
    const int n0 = blockIdx.x * 32, k0 = blockIdx.y * 32;
    const int tx = threadIdx.x, ty = threadIdx.y;
    #pragma unroll
    for (int j = 0; j < 32; j += 8)
        tile[ty + j][tx] = W[(size_t)(k0 + ty + j) * N + n0 + tx];
    __syncthreads();
    #pragma unroll
    for (int j = 0; j < 32; j += 8)
        WT[(size_t)(n0 + ty + j) * D + k0 + tx] = __float2half_rn(tile[tx][ty + j]);
}

// ---------------------------------------------------------------------------
// FP16 mma.sync GEMM with ldmatrix fragments, BK=32, 4-STAGE cp.async
// (R14-exact, 89us on QKV).
// ---------------------------------------------------------------------------
#define GP 40
#define G_ST (128 * GP)                    // halves per operand per stage
#define GEMM_SMEM (4 * 2 * G_ST * 2)       // 81920 B

__device__ __forceinline__ void gm_load_chunk(
    uint32_t aS, uint32_t bS,
    const __half* __restrict__ A, const __half* __restrict__ WT,
    int bm, int bn, int k0, int tid)
{
    #pragma unroll
    for (int j = 0; j < 2; j++) {
        const int idx = tid + j * 256;
        const int r = idx >> 2, c = idx & 3;
        CP_ASYNC16(aS + (uint32_t)(r * GP + c * 8) * 2u,
                   A + (size_t)(bm + r) * D + k0 + c * 8);
        CP_ASYNC16(bS + (uint32_t)(r * GP + c * 8) * 2u,
                   WT + (size_t)(bn + r) * D + k0 + c * 8);
    }
}

__global__ __launch_bounds__(256, 2) void gemm_h_kernel(
    const __half* __restrict__ A, const __half* __restrict__ WT,
    const float* __restrict__ bias, float* __restrict__ Cf,
    uint32_t* __restrict__ Ch, int N)
{
    extern __shared__ char smc[];
    const uint32_t base = smem_u32(smc);
    uint32_t aB[4], bB[4];
    #pragma unroll
    for (int s = 0; s < 4; s++) {
        aB[s] = base + (uint32_t)s * (G_ST * 2);
        bB[s] = base + 4u * (G_ST * 2) + (uint32_t)s * (G_ST * 2);
    }

    const int tid = threadIdx.x;
    const int wid = tid >> 5, lane = tid & 31;
    const int gID = lane >> 2, tg = lane & 3;
    const int rowl = lane & 7, grp = lane >> 3;
    const int bm = blockIdx.y * 128, bn = blockIdx.x * 128;
    const int wm = (wid & 3) * 32, wn = (wid >> 2) * 64;

    const uint32_t aOff = (uint32_t)(((grp & 1) * 8 + rowl) * GP + (grp >> 1) * 8);
    const uint32_t bOff = (uint32_t)(((grp >> 1) * 8 + rowl) * GP + (grp & 1) * 8);

    float acc[2][8][4];
    #pragma unroll
    for (int im = 0; im < 2; im++)
        #pragma unroll
        for (int n = 0; n < 8; n++)
            #pragma unroll
            for (int j = 0; j < 4; j++) acc[im][n][j] = 0.f;

    #pragma unroll
    for (int pi = 0; pi < 3; pi++) {
        gm_load_chunk(aB[pi], bB[pi], A, WT, bm, bn, pi * 32, tid);
        CP_COMMIT();
    }

    #pragma unroll 4
    for (int i = 0; i < 32; i++) {
        const int s = i & 3;
        CP_WAIT2();
        __syncthreads();
        if (i + 3 < 32)
            gm_load_chunk(aB[(i + 3) & 3], bB[(i + 3) & 3], A, WT, bm, bn,
                          (i + 3) * 32, tid);
        CP_COMMIT();   // unconditional: keeps group-age invariant at tail

        const uint32_t aS = aB[s], bS = bB[s];
        #pragma unroll
        for (int ks = 0; ks < 2; ks++) {
            uint32_t af[2][4];
            #pragma unroll
            for (int im = 0; im < 2; im++)
                LDSM_X4(af[im][0], af[im][1], af[im][2], af[im][3],
                        aS + (aOff + (uint32_t)((wm + im * 16) * GP + ks * 16)) * 2u);
            #pragma unroll
            for (int np = 0; np < 4; np++) {
                uint32_t b0, b1, b2, b3;
                LDSM_X4(b0, b1, b2, b3,
                        bS + (bOff + (uint32_t)((wn + np * 16) * GP + ks * 16)) * 2u);
                #pragma unroll
                for (int im = 0; im < 2; im++) {
                    mma_f16(acc[im][2*np][0], acc[im][2*np][1],
                            acc[im][2*np][2], acc[im][2*np][3],
                            af[im][0], af[im][1], af[im][2], af[im][3], b0, b1);
                    mma_f16(acc[im][2*np+1][0], acc[im][2*np+1][1],
                            acc[im][2*np+1][2], acc[im][2*np+1][3],
                            af[im][0], af[im][1], af[im][2], af[im][3], b2, b3);
                }
            }
        }
    }

    #pragma unroll
    for (int im = 0; im < 2; im++) {
        const int r0 = bm + wm + im * 16 + gID;
        #pragma unroll
        for (int n = 0; n < 8; n++) {
            const int col = bn + wn + n * 8 + 2 * tg;
            float v0 = acc[im][n][0], v1 = acc[im][n][1];
            float v2 = acc[im][n][2], v3 = acc[im][n][3];
            if (bias) {
                const float b0 = bias[col], b1 = bias[col + 1];
                v0 += b0; v1 += b1; v2 += b0; v3 += b1;
            }
            if (Ch) {
                Ch[((size_t)r0 * N + col) >> 1]       = packh2(v0, v1);
                Ch[((size_t)(r0 + 8) * N + col) >> 1] = packh2(v2, v3);
            } else {
                *(float2*)&Cf[(size_t)r0 * N + col]       = make_float2(v0, v1);
                *(float2*)&Cf[(size_t)(r0 + 8) * N + col] = make_float2(v2, v3);
            }
        }
    }
}

// ---------------------------------------------------------------------------
// FP16 mma.sync flash attention — R11 compute body, R14-style 4-STAGE
// cp.async K/V pipeline (one __syncthreads per tile, wait_group 2,
// unconditional commits). smem 73.7KB -> 2 CTAs/SM.
// Block: 256 threads / 8 warps, 128 queries (16/warp), 64-key tiles.
// grid (S/128, HEADS, B)
// ---------------------------------------------------------------------------
#define KPH 72
#define KV_TILE_B (64 * KPH * 2)            // 9216 B per K or V stage
#define ATTN_SMEM (4 * 2 * KV_TILE_B)       // 73728 B

__device__ __forceinline__ void at_load_tile(
    uint32_t kS, uint32_t vS,
    const __half* __restrict__ kbase, const __half* __restrict__ vbase,
    int r0, int tid)
{
    #pragma unroll
    for (int j = 0; j < 2; j++) {
        const int idx = tid + j * 256;
        const int r = idx >> 3, c = idx & 7;
        CP_ASYNC16(kS + (uint32_t)(r * KPH + c * 8) * 2u,
                   kbase + (size_t)(r0 + r) * D3 + c * 8);
        CP_ASYNC16(vS + (uint32_t)(r * KPH + c * 8) * 2u,
                   vbase + (size_t)(r0 + r) * D3 + c * 8);
    }
}

__global__ __launch_bounds__(256, 2) void attn_kernel(
    const __half* __restrict__ qkv, uint32_t* __restrict__ ctxh)
{
    extern __shared__ char smc[];
    const uint32_t base = smem_u32(smc);
    uint32_t kB[4], vB[4];
    #pragma unroll
    for (int s = 0; s < 4; s++) {
        kB[s] = base + (uint32_t)s * KV_TILE_B;
        vB[s] = base + 4u * KV_TILE_B + (uint32_t)s * KV_TILE_B;
    }

    const int tid = threadIdx.x;
    const int wid = tid >> 5, lane = tid & 31;
    const int gID = lane >> 2, tg = lane & 3;
    const int rowl = lane & 7, grp = lane >> 3;
    const int h = blockIdx.y, bb = blockIdx.z;
    const int qbase = blockIdx.x * 128 + wid * 16;

    const __half* qp = qkv + (size_t)(bb * S + qbase) * D3 + h * DH;
    const __half* kbase = qkv + (size_t)bb * S * D3 + INNER + h * DH;
    const __half* vbase = kbase + INNER;

    // Q fragments: raw fp16, u32 pair slots
    uint32_t qa[4][4];
    #pragma unroll
    for (int ks = 0; ks < 4; ks++) {
        qa[ks][0] = *(const uint32_t*)(qp + (size_t)gID * D3 + 16 * ks + 2 * tg);
        qa[ks][1] = *(const uint32_t*)(qp + (size_t)(gID + 8) * D3 + 16 * ks + 2 * tg);
        qa[ks][2] = *(const uint32_t*)(qp + (size_t)gID * D3 + 16 * ks + 2 * tg + 8);
        qa[ks][3] = *(const uint32_t*)(qp + (size_t)(gID + 8) * D3 + 16 * ks + 2 * tg + 8);
    }

    const uint32_t k_lane_off = (uint32_t)((((grp >> 1) * 8 + rowl) * KPH + (grp & 1) * 8) * 2);
    const uint32_t v_lane_off = (uint32_t)((((grp & 1) * 8 + rowl) * KPH + (grp >> 1) * 8) * 2);

    float o[8][4];
    #pragma unroll
    for (int n = 0; n < 8; n++)
        #pragma unroll
        for (int j = 0; j < 4; j++) o[n][j] = 0.f;
    float m0 = -1e30f, m1 = -1e30f, l0 = 0.f, l1 = 0.f;
    const float CS = QSCALE_LOG2E;

    // prologue: tiles 0,1,2 -> stages 0,1,2
    #pragma unroll
    for (int pi = 0; pi < 3; pi++) {
        at_load_tile(kB[pi], vB[pi], kbase, vbase, pi * 64, tid);
        CP_COMMIT();
    }

    #pragma unroll 4
    for (int i = 0; i < 32; i++) {
        const int s = i & 3;
        CP_WAIT2();
        __syncthreads();
        if (i + 3 < 32)
            at_load_tile(kB[(i + 3) & 3], vB[(i + 3) & 3], kbase, vbase,
                         (i + 3) * 64, tid);
        CP_COMMIT();   // unconditional: keeps group-age invariant at tail

        // ---- S = Q @ K^T ----
        float sa[8][4];
        #pragma unroll
        for (int n = 0; n < 8; n++)
            #pragma unroll
            for (int j = 0; j < 4; j++) sa[n][j] = 0.f;
        #pragma unroll
        for (int ks = 0; ks < 4; ks++) {
            #pragma unroll
            for (int np = 0; np < 4; np++) {
                uint32_t r0, r1, r2, r3;
                LDSM_X4(r0, r1, r2, r3,
                        kB[s] + k_lane_off + (uint32_t)((np * 16 * KPH + ks * 16) * 2));
                mma_f16(sa[2*np][0], sa[2*np][1], sa[2*np][2], sa[2*np][3],
                        qa[ks][0], qa[ks][1], qa[ks][2], qa[ks][3], r0, r1);
                mma_f16(sa[2*np+1][0], sa[2*np+1][1], sa[2*np+1][2], sa[2*np+1][3],
                        qa[ks][0], qa[ks][1], qa[ks][2], qa[ks][3], r2, r3);
            }
        }

        // ---- online softmax (base 2, scale via fma; P packed to half2) ----
        float rmax0 = sa[0][0], rmax1 = sa[0][2];
        #pragma unroll
        for (int n = 0; n < 8; n++) {
            rmax0 = fmaxf(rmax0, fmaxf(sa[n][0], sa[n][1]));
            rmax1 = fmaxf(rmax1, fmaxf(sa[n][2], sa[n][3]));
        }
        rmax0 = fmaxf(rmax0, __shfl_xor_sync(0xffffffffu, rmax0, 1));
        rmax0 = fmaxf(rmax0, __shfl_xor_sync(0xffffffffu, rmax0, 2));
        rmax1 = fmaxf(rmax1, __shfl_xor_sync(0xffffffffu, rmax1, 1));
        rmax1 = fmaxf(rmax1, __shfl_xor_sync(0xffffffffu, rmax1, 2));
        const float nm0 = fmaxf(m0, rmax0 * CS), nm1 = fmaxf(m1, rmax1 * CS);
        const float c0 = ex2f(m0 - nm0), c1 = ex2f(m1 - nm1);
        m0 = nm0; m1 = nm1;
        float s0 = 0.f, s1 = 0.f;
        uint32_t p01[8], p23[8];
        #pragma unroll
        for (int n = 0; n < 8; n++) {
            const float p0 = ex2f(fmaf(sa[n][0], CS, -m0));
            const float p1 = ex2f(fmaf(sa[n][1], CS, -m0));
            const float p2 = ex2f(fmaf(sa[n][2], CS, -m1));
            const float p3 = ex2f(fmaf(sa[n][3], CS, -m1));
            s0 += p0 + p1; s1 += p2 + p3;
            p01[n] = packh2(p0, p1);
            p23[n] = packh2(p2, p3);
            o[n][0] *= c0; o[n][1] *= c0; o[n][2] *= c1; o[n][3] *= c1;
        }
        s0 += __shfl_xor_sync(0xffffffffu, s0, 1);
        s0 += __shfl_xor_sync(0xffffffffu, s0, 2);
        s1 += __shfl_xor_sync(0xffffffffu, s1, 1);
        s1 += __shfl_xor_sync(0xffffffffu, s1, 2);
        l0 = l0 * c0 + s0;
        l1 = l1 * c1 + s1;

        // ---- O += P @ V (ldmatrix.trans V fragments) ----
        #pragma unroll
        for (int kc = 0; kc < 4; kc++) {
            const uint32_t a0 = p01[2*kc], a1 = p23[2*kc];
            const uint32_t a2 = p01[2*kc+1], a3 = p23[2*kc+1];
            #pragma unroll
            for (int cp = 0; cp < 4; cp++) {
                uint32_t r0, r1, r2, r3;
                LDSM_X4_T(r0, r1, r2, r3,
                          vB[s] + v_lane_off + (uint32_t)((kc * 16 * KPH + cp * 16) * 2));
                mma_f16(o[2*cp][0], o[2*cp][1], o[2*cp][2], o[2*cp][3],
                        a0, a1, a2, a3, r0, r1);
                mma_f16(o[2*cp+1][0], o[2*cp+1][1], o[2*cp+1][2], o[2*cp+1][3],
                        a0, a1, a2, a3, r2, r3);
            }
        }
    }

    // epilogue: normalize, write fp16 half2 pairs
    const float inv0 = 1.f / l0, inv1 = 1.f / l1;
    const size_t grow = (size_t)(bb * S + qbase + gID);
    #pragma unroll
    for (int n = 0; n < 8; n++) {
        const int col = h * DH + n * 8 + 2 * tg;
        ctxh[(grow * INNER + col) >> 1] =
            packh2(o[n][0] * inv0, o[n][1] * inv0);
        ctxh[((grow + 8) * INNER + col) >> 1] =
            packh2(o[n][2] * inv1, o[n][3] * inv1);
    }
}

// ---------------------------------------------------------------------------
extern "C" void kernel_launch(void* const* d_in, const int* in_sizes, int n_in,
                              void* d_out, int out_size)
{
    const float* x        = (const float*)d_in[0];
    const float* ln_gamma = (const float*)d_in[1];
    const float* ln_beta  = (const float*)d_in[2];
    const float* w_qkv    = (const float*)d_in[3];
    const float* w_out    = (const float*)d_in[4];
    const float* b_out    = (const float*)d_in[5];
    float* out = (float*)d_out;

    void* sp = nullptr;
    cudaGetSymbolAddress(&sp, g_scratch);
    float* base = (float*)sp;
    uint32_t* xnh  = (uint32_t*)base;                        // ROWS*D halves
    uint32_t* qkvh = xnh + (size_t)ROWS * D / 2;             // ROWS*D3 halves
    uint32_t* ctxh = qkvh + (size_t)ROWS * D3 / 2;           // ROWS*D halves
    __half*   wqT  = (__half*)(ctxh + (size_t)ROWS * D / 2); // [D3][D] halves
    __half*   woT  = wqT + (size_t)D3 * D;                   // [D][D] halves

    cudaFuncSetAttribute(gemm_h_kernel, cudaFuncAttributeMaxDynamicSharedMemorySize, GEMM_SMEM);
    cudaFuncSetAttribute(attn_kernel, cudaFuncAttributeMaxDynamicSharedMemorySize, ATTN_SMEM);

    // transpose + pack weights to fp16 [N][K]
    pack_wT_kernel<<<dim3(D3 / 32, D / 32), dim3(32, 8)>>>(w_qkv, wqT, D3);
    pack_wT_kernel<<<dim3(D / 32, D / 32), dim3(32, 8)>>>(w_out, woT, D);

    // 1. LayerNorm (fp16 output)
    ln_kernel<<<ROWS, 256>>>(x, ln_gamma, ln_beta, xnh);

    // 2. QKV projection (fp16 tensor cores + ldmatrix, 4-stage, fp16 output)
    gemm_h_kernel<<<dim3(D3 / 128, ROWS / 128), 256, GEMM_SMEM>>>(
        (const __half*)xnh, wqT, nullptr, nullptr, qkvh, D3);

    // 3. Flash attention (fp16 + ldmatrix, 4-stage K/V, fp16 ctx output)
    attn_kernel<<<dim3(S / 128, HEADS, B), 256, ATTN_SMEM>>>(
        (const __half*)qkvh, ctxh);

    // 4. Output projection + bias (fp16 tensor cores + ldmatrix, fp32 out)
    gemm_h_kernel<<<dim3(D / 128, ROWS / 128), 256, GEMM_SMEM>>>(
        (const __half*)ctxh, woT, b_out, out, nullptr, D);
}